// round 14
// baseline (speedup 1.0000x reference)
#include <cuda_runtime.h>
#include <cuda_bf16.h>
#include <math.h>

#define D_MODEL 512
#define N_EXP   8
#define HIDDEN  2048
#define T_MAX   8192
#define TILE_M  128
#define MAX_TILES (T_MAX/TILE_M + N_EXP)

typedef unsigned int u32;
typedef unsigned short u16;

// swizzled smem: each region = 128 logical rows x 32 u16 (64B), packed as
// 64 phys rows x 128B with XOR swizzle; region = 8192 B, stage = 4 regions.
#define R_AH 0
#define R_AL 8192
#define R_BH 16384
#define R_BL 24576
#define BUF_B 32768
#define NSTAGE 3
#define SMEM_TOT (NSTAGE * BUF_B)   // 98304 B

// ---------------- scratch (device globals, no allocation) ----------------
__device__ __align__(16) u16 g_xhi[(size_t)T_MAX * D_MODEL];
__device__ __align__(16) u16 g_xlo[(size_t)T_MAX * D_MODEL];
__device__ __align__(16) u16 g_w1hi[(size_t)N_EXP * HIDDEN * D_MODEL]; // [E][H][D] transposed
__device__ __align__(16) u16 g_w1lo[(size_t)N_EXP * HIDDEN * D_MODEL];
__device__ __align__(16) u16 g_w2hi[(size_t)N_EXP * D_MODEL * HIDDEN]; // [E][D][H] transposed
__device__ __align__(16) u16 g_w2lo[(size_t)N_EXP * D_MODEL * HIDDEN];
__device__ __align__(16) u16 g_hhi[(size_t)T_MAX * HIDDEN];
__device__ __align__(16) u16 g_hlo[(size_t)T_MAX * HIDDEN];
__device__ int    g_perm[T_MAX];
__device__ int    g_tok_exp[T_MAX];
__device__ float  g_wsel[T_MAX];
__device__ double g_imp[N_EXP];
__device__ int    g_tile_exp[MAX_TILES];
__device__ int    g_tile_row0[MAX_TILES];
__device__ int    g_tile_rows[MAX_TILES];
__device__ int    g_ntiles;

__device__ __forceinline__ float gelu_exact(float v) {
    return 0.5f * v * (1.0f + erff(v * 0.70710678118654752440f));
}
__device__ __forceinline__ u32 smem_u32(const void* p) {
    u32 a;
    asm("{ .reg .u64 t; cvta.to.shared.u64 t, %1; cvt.u32.u64 %0, t; }" : "=r"(a) : "l"(p));
    return a;
}
// swizzle: logical (row r in 0..127, 16B unit c in 0..3) -> byte offset in region
__device__ __forceinline__ u32 swz(u32 r, u32 c) {
    return ((r >> 1) << 7) | (((((r & 1) << 2) | c) ^ ((r >> 1) & 7)) << 4);
}

// ---- portable PTX (sm_80+): cp.async, ldmatrix, mma ----
#define CP16(d, s)  asm volatile("cp.async.cg.shared.global [%0], [%1], 16;" :: "r"(d), "l"(s))
#define CPCOMMIT()  asm volatile("cp.async.commit_group;" ::: "memory")
#define CPWAIT1()   asm volatile("cp.async.wait_group 1;" ::: "memory")
#define CPWAIT0()   asm volatile("cp.async.wait_group 0;" ::: "memory")

#define LDM4(r, a) \
    asm volatile("ldmatrix.sync.aligned.m8n8.x4.shared.b16 {%0,%1,%2,%3}, [%4];" \
        : "=r"((r)[0]), "=r"((r)[1]), "=r"((r)[2]), "=r"((r)[3]) : "r"(a))

#define MMA(ac, a0, a1, a2, a3, b0, b1) \
    asm volatile("mma.sync.aligned.m16n8k16.row.col.f32.bf16.bf16.f32 " \
        "{%0,%1,%2,%3},{%4,%5,%6,%7},{%8,%9},{%0,%1,%2,%3};" \
        : "+f"((ac)[0]), "+f"((ac)[1]), "+f"((ac)[2]), "+f"((ac)[3]) \
        : "r"(a0), "r"(a1), "r"(a2), "r"(a3), "r"(b0), "r"(b1))

// ---------------- kernel 0 ----------------
__global__ void init_kernel() {
    if (threadIdx.x < N_EXP) g_imp[threadIdx.x] = 0.0;
}

// ---------------- kernel 1: router (proven: shared float + global double atomics) ----
__global__ void __launch_bounds__(256) router_kernel(
    const float* __restrict__ x, const float* __restrict__ u,
    const float* __restrict__ rw, const float* __restrict__ rb, int T)
{
    __shared__ float s_imp[N_EXP];
    if (threadIdx.x < N_EXP) s_imp[threadIdx.x] = 0.0f;
    __syncthreads();

    int t    = blockIdx.x * 8 + (threadIdx.x >> 5);
    int lane = threadIdx.x & 31;

    if (t < T) {
        float acc[8];
        #pragma unroll
        for (int e = 0; e < 8; e++) acc[e] = 0.0f;
        const float* xr = x + (size_t)t * D_MODEL;
        for (int k = lane; k < D_MODEL; k += 32) {
            float xv = xr[k];
            float4 wa = *(const float4*)(rw + k * 8);
            float4 wb = *(const float4*)(rw + k * 8 + 4);
            acc[0] += xv * wa.x; acc[1] += xv * wa.y;
            acc[2] += xv * wa.z; acc[3] += xv * wa.w;
            acc[4] += xv * wb.x; acc[5] += xv * wb.y;
            acc[6] += xv * wb.z; acc[7] += xv * wb.w;
        }
        #pragma unroll
        for (int e = 0; e < 8; e++) {
            #pragma unroll
            for (int off = 16; off > 0; off >>= 1)
                acc[e] += __shfl_down_sync(0xffffffffu, acc[e], off);
        }
        if (lane == 0) {
            float logits[8];
            #pragma unroll
            for (int e = 0; e < 8; e++) logits[e] = acc[e] + rb[e];
            float m = logits[0];
            #pragma unroll
            for (int e = 1; e < 8; e++) m = fmaxf(m, logits[e]);
            float p[8]; float se = 0.0f;
            #pragma unroll
            for (int e = 0; e < 8; e++) { p[e] = expf(logits[e] - m); se += p[e]; }
            float inv = 1.0f / se;
            #pragma unroll
            for (int e = 0; e < 8; e++) atomicAdd(&s_imp[e], p[e] * inv);

            const float* ur = u + (size_t)t * 8;
            float z[8]; int best = 0; float zb = -1e30f;
            #pragma unroll
            for (int e = 0; e < 8; e++) {
                float g = -logf(-logf(ur[e]) + 1e-10f);
                z[e] = logits[e] + g;
                if (z[e] > zb) { zb = z[e]; best = e; }
            }
            float s2 = 0.0f;
            #pragma unroll
            for (int e = 0; e < 8; e++) s2 += expf(z[e] - zb);
            float y = 1.0f / s2;
            g_tok_exp[t] = best;
            g_wsel[t]    = (1.0f - y) + y;
        }
    }
    __syncthreads();
    if (threadIdx.x < N_EXP)
        atomicAdd(&g_imp[threadIdx.x], (double)s_imp[threadIdx.x]);
}

// ---------------- kernel 2: scatter + tiles (warp-parallel, atomic-free rank) -----------
// 1 block, 1024 threads = 32 warps; warp w owns tokens [w*T/32, (w+1)*T/32).
__global__ void __launch_bounds__(1024) scatter_kernel(int T) {
    __shared__ int s_wcnt[32][N_EXP];
    __shared__ int s_wb[32][N_EXP];
    __shared__ int s_tot[N_EXP];
    __shared__ int s_base[N_EXP];
    int tid  = threadIdx.x;
    int w    = tid >> 5, lane = tid & 31;
    int seg  = T / 32;          // 256
    int rounds = seg / 32;      // 8

    if (lane < N_EXP) s_wcnt[w][lane] = 0;
    __syncthreads();

    // pass A: per-warp histograms (contention only within one warp's row)
    int myexp[8];
    for (int r = 0; r < rounds; r++) {
        int t = w * seg + r * 32 + lane;
        int e = g_tok_exp[t];
        myexp[r] = e;
        atomicAdd(&s_wcnt[w][e], 1);
    }
    __syncthreads();

    // totals per expert
    if (w == 0 && lane < N_EXP) {
        int tot = 0;
        for (int ww = 0; ww < 32; ww++) tot += s_wcnt[ww][lane];
        s_tot[lane] = tot;
    }
    __syncthreads();

    // expert bases + tile table (thread 0, trivial)
    if (tid == 0) {
        int off = 0, nt = 0;
        for (int e = 0; e < N_EXP; e++) {
            s_base[e] = off;
            int c = s_tot[e];
            for (int m = 0; m < c; m += TILE_M) {
                g_tile_exp[nt]  = e;
                g_tile_row0[nt] = off + m;
                g_tile_rows[nt] = min(TILE_M, c - m);
                nt++;
            }
            off += c;
        }
        g_ntiles = nt;
    }
    __syncthreads();

    // per-warp bases (exclusive prefix over warps, per expert)
    if (w == 0 && lane < N_EXP) {
        int run = s_base[lane];
        for (int ww = 0; ww < 32; ww++) {
            s_wb[ww][lane] = run;
            run += s_wcnt[ww][lane];
        }
    }
    __syncthreads();

    // pass B: ballot+popc rank assignment (no atomics)
    int wb[N_EXP];
    #pragma unroll
    for (int e = 0; e < N_EXP; e++) wb[e] = s_wb[w][e];
    for (int r = 0; r < rounds; r++) {
        int t = w * seg + r * 32 + lane;
        int e = myexp[r];
        int pos = 0;
        #pragma unroll
        for (int ee = 0; ee < N_EXP; ee++) {
            unsigned mask = __ballot_sync(0xffffffffu, e == ee);
            if (e == ee)
                pos = wb[ee] + __popc(mask & ((1u << lane) - 1u));
            wb[ee] += __popc(mask);
        }
        g_perm[pos] = t;
    }
}

// ---------------- kernel 3: gather + hi/lo convert x (perm order) ----------------
__global__ void __launch_bounds__(256) convx_kernel(const float* __restrict__ x, int T) {
    int idx = blockIdx.x * 256 + threadIdx.x;
    if (idx >= T * (D_MODEL / 4)) return;
    int row  = idx >> 7;
    int col4 = idx & 127;
    int tok  = g_perm[row];
    float4 v = ((const float4*)x)[(size_t)tok * 128 + col4];
    __nv_bfloat16 h0 = __float2bfloat16(v.x), h1 = __float2bfloat16(v.y);
    __nv_bfloat16 h2 = __float2bfloat16(v.z), h3 = __float2bfloat16(v.w);
    ushort4 H, L;
    H.x = __bfloat16_as_ushort(h0); H.y = __bfloat16_as_ushort(h1);
    H.z = __bfloat16_as_ushort(h2); H.w = __bfloat16_as_ushort(h3);
    L.x = __bfloat16_as_ushort(__float2bfloat16(v.x - __bfloat162float(h0)));
    L.y = __bfloat16_as_ushort(__float2bfloat16(v.y - __bfloat162float(h1)));
    L.z = __bfloat16_as_ushort(__float2bfloat16(v.z - __bfloat162float(h2)));
    L.w = __bfloat16_as_ushort(__float2bfloat16(v.w - __bfloat162float(h3)));
    size_t o = (size_t)row * D_MODEL + col4 * 4;
    *(ushort4*)(g_xhi + o) = H;
    *(ushort4*)(g_xlo + o) = L;
}

// ---------------- kernel 4: transpose + hi/lo convert weights ----------------
// Destination device globals referenced INSIDE the kernel.
template<int R, int C, int WHICH>
__global__ void __launch_bounds__(256) convT_kernel(const float* __restrict__ src)
{
    __shared__ float tile[32][33];
    int e  = blockIdx.z;
    int c0 = blockIdx.x * 32, r0 = blockIdx.y * 32;
    int tx = threadIdx.x, ty = threadIdx.y;
    #pragma unroll
    for (int i = 0; i < 4; i++) {
        int r = r0 + ty + i * 8;
        tile[ty + i * 8][tx] = src[((size_t)e * R + r) * C + c0 + tx];
    }
    __syncthreads();
    u16* dhi = (WHICH == 1) ? g_w1hi : g_w2hi;
    u16* dlo = (WHICH == 1) ? g_w1lo : g_w2lo;
    #pragma unroll
    for (int i = 0; i < 4; i++) {
        int c = c0 + ty + i * 8;
        int r = r0 + tx;
        float v = tile[tx][ty + i * 8];
        __nv_bfloat16 h = __float2bfloat16(v);
        float lo = v - __bfloat162float(h);
        size_t o = ((size_t)e * C + c) * R + r;
        dhi[o] = __bfloat16_as_ushort(h);
        dlo[o] = __bfloat16_as_ushort(__float2bfloat16(lo));
    }
}

// ---------------- GEMM mainloop: 3-stage cp.async, swizzled smem, 1 sync/chunk ---------
// CTA tile 128x128, 8 warps (4m x 2n), warp tile 32x64, K-chunk 32.
__device__ __forceinline__ void run_gemm(
    u32 sb, const u16* aH, const u16* aL, const u16* bH, const u16* bL,
    int NC, int tid, float acc[2][8][4])
{
    int l  = tid & 31;
    int wm = (tid >> 5) & 3;
    int wn = (tid >> 5) >> 2;

    u32 r_st = (u32)(tid >> 1);
    u32 u0   = (u32)(tid & 1) * 2;
    u32 d0 = swz(r_st, u0);
    u32 d1 = swz(r_st, u0 + 1);

    u32 r_a = (u32)(wm * 32 + (l & 7) + ((l & 8) ? 8 : 0));
    u32 ca  = (l & 16) ? 1u : 0u;
    u32 r_b = (u32)(wn * 64 + (l & 7) + ((l & 16) ? 8 : 0));
    u32 cb  = (l & 8) ? 1u : 0u;

    #define ISSUE(c, st) do { \
        u32 base = sb + (u32)(st) * BUF_B; \
        const u16* s_; \
        s_ = aH + (size_t)(c) * 32; CP16(base + R_AH + d0, s_); CP16(base + R_AH + d1, s_ + 8); \
        s_ = aL + (size_t)(c) * 32; CP16(base + R_AL + d0, s_); CP16(base + R_AL + d1, s_ + 8); \
        s_ = bH + (size_t)(c) * 32; CP16(base + R_BH + d0, s_); CP16(base + R_BH + d1, s_ + 8); \
        s_ = bL + (size_t)(c) * 32; CP16(base + R_BL + d0, s_); CP16(base + R_BL + d1, s_ + 8); \
        CPCOMMIT(); \
    } while (0)

    ISSUE(0, 0);
    if (NC > 1) ISSUE(1, 1);

    int st  = 0;
    int ist = 2;
    for (int c = 0; c < NC; c++) {
        if (c + 1 < NC) { CPWAIT1(); } else { CPWAIT0(); }
        __syncthreads();
        u32 buf = sb + (u32)st * BUF_B;

        #pragma unroll
        for (int kk = 0; kk < 2; kk++) {
            u32 cc = (u32)kk * 2;
            u32 ah0[4], ah1[4], al0[4], al1[4];
            LDM4(ah0, buf + R_AH + swz(r_a,      cc + ca));
            LDM4(ah1, buf + R_AH + swz(r_a + 16, cc + ca));
            LDM4(al0, buf + R_AL + swz(r_a,      cc + ca));
            LDM4(al1, buf + R_AL + swz(r_a + 16, cc + ca));

            #pragma unroll
            for (int p = 0; p < 4; p++) {
                u32 bh[4], bl[4];
                u32 so = swz(r_b + (u32)p * 16, cc + cb);
                LDM4(bh, buf + R_BH + so);
                LDM4(bl, buf + R_BL + so);
                int n0 = p * 2;
                MMA(acc[0][n0],   ah0[0], ah0[1], ah0[2], ah0[3], bh[0], bh[1]);
                MMA(acc[0][n0],   ah0[0], ah0[1], ah0[2], ah0[3], bl[0], bl[1]);
                MMA(acc[0][n0],   al0[0], al0[1], al0[2], al0[3], bh[0], bh[1]);
                MMA(acc[0][n0+1], ah0[0], ah0[1], ah0[2], ah0[3], bh[2], bh[3]);
                MMA(acc[0][n0+1], ah0[0], ah0[1], ah0[2], ah0[3], bl[2], bl[3]);
                MMA(acc[0][n0+1], al0[0], al0[1], al0[2], al0[3], bh[2], bh[3]);
                MMA(acc[1][n0],   ah1[0], ah1[1], ah1[2], ah1[3], bh[0], bh[1]);
                MMA(acc[1][n0],   ah1[0], ah1[1], ah1[2], ah1[3], bl[0], bl[1]);
                MMA(acc[1][n0],   al1[0], al1[1], al1[2], al1[3], bh[0], bh[1]);
                MMA(acc[1][n0+1], ah1[0], ah1[1], ah1[2], ah1[3], bh[2], bh[3]);
                MMA(acc[1][n0+1], ah1[0], ah1[1], ah1[2], ah1[3], bl[2], bl[3]);
                MMA(acc[1][n0+1], al1[0], al1[1], al1[2], al1[3], bh[2], bh[3]);
            }
        }
        if (c + 2 < NC) ISSUE(c + 2, ist);
        st  = (st  == 2) ? 0 : st  + 1;
        ist = (ist == 2) ? 0 : ist + 1;
    }
    #undef ISSUE
}

// ---------------- kernel 5: FFN1 ----------------
__global__ void __launch_bounds__(256, 2) ffn1_kernel(const float* __restrict__ b1)
{
    int tile = blockIdx.y;
    if (tile >= g_ntiles) return;
    int e    = g_tile_exp[tile];
    int row0 = g_tile_row0[tile];
    int rows = g_tile_rows[tile];
    int n0b  = blockIdx.x * 128;

    extern __shared__ u16 smem_dyn[];
    u32 sb  = smem_u32(smem_dyn);
    int tid = threadIdx.x;
    int seg = (tid & 1) * 16;

    int arow = row0 + min(tid >> 1, rows - 1);
    const u16* aH = g_xhi + (size_t)arow * D_MODEL + seg;
    const u16* aL = g_xlo + (size_t)arow * D_MODEL + seg;
    size_t boff = ((size_t)e * HIDDEN + n0b + (tid >> 1)) * D_MODEL + seg;
    const u16* bH = g_w1hi + boff;
    const u16* bL = g_w1lo + boff;

    float acc[2][8][4];
    #pragma unroll
    for (int i = 0; i < 2; i++)
        #pragma unroll
        for (int j = 0; j < 8; j++)
            #pragma unroll
            for (int q = 0; q < 4; q++) acc[i][j][q] = 0.0f;

    run_gemm(sb, aH, aL, bH, bL, D_MODEL / 32, tid, acc);

    int l  = tid & 31;
    int wm = (tid >> 5) & 3;
    int wn = (tid >> 5) >> 2;
    int g  = l >> 2;
    int t  = l & 3;
    const float* be = b1 + (size_t)e * HIDDEN + n0b + wn * 64;

    #pragma unroll
    for (int mf = 0; mf < 2; mf++)
        #pragma unroll
        for (int rr = 0; rr < 2; rr++) {
            int m = wm * 32 + mf * 16 + g + rr * 8;
            if (m < rows) {
                size_t ro = (size_t)(row0 + m) * HIDDEN + n0b + wn * 64;
                #pragma unroll
                for (int nb = 0; nb < 8; nb++) {
                    int nc = nb * 8 + t * 2;
                    float2 bb = *(const float2*)(be + nc);
                    float f0 = gelu_exact(acc[mf][nb][rr * 2 + 0] + bb.x);
                    float f1 = gelu_exact(acc[mf][nb][rr * 2 + 1] + bb.y);
                    __nv_bfloat16 h0 = __float2bfloat16(f0);
                    __nv_bfloat16 h1 = __float2bfloat16(f1);
                    u32 hp = (u32)__bfloat16_as_ushort(h0) | ((u32)__bfloat16_as_ushort(h1) << 16);
                    u16 l0 = __bfloat16_as_ushort(__float2bfloat16(f0 - __bfloat162float(h0)));
                    u16 l1 = __bfloat16_as_ushort(__float2bfloat16(f1 - __bfloat162float(h1)));
                    u32 lp = (u32)l0 | ((u32)l1 << 16);
                    *(u32*)(g_hhi + ro + nc) = hp;
                    *(u32*)(g_hlo + ro + nc) = lp;
                }
            }
        }
}

// ---------------- kernel 6: FFN2 ----------------
__global__ void __launch_bounds__(256, 2) ffn2_kernel(
    const float* __restrict__ b2, float* __restrict__ out)
{
    int tile = blockIdx.y;
    if (tile >= g_ntiles) return;
    int e    = g_tile_exp[tile];
    int row0 = g_tile_row0[tile];
    int rows = g_tile_rows[tile];
    int n0b  = blockIdx.x * 128;

    extern __shared__ u16 smem_dyn[];
    u32 sb  = smem_u32(smem_dyn);
    int tid = threadIdx.x;
    int seg = (tid & 1) * 16;

    int arow = row0 + min(tid >> 1, rows - 1);
    const u16* aH = g_hhi + (size_t)arow * HIDDEN + seg;
    const u16* aL = g_hlo + (size_t)arow * HIDDEN + seg;
    size_t boff = ((size_t)e * D_MODEL + n0b + (tid >> 1)) * HIDDEN + seg;
    const u16* bH = g_w2hi + boff;
    const u16* bL = g_w2lo + boff;

    float acc[2][8][4];
    #pragma unroll
    for (int i = 0; i < 2; i++)
        #pragma unroll
        for (int j = 0; j < 8; j++)
            #pragma unroll
            for (int q = 0; q < 4; q++) acc[i][j][q] = 0.0f;

    run_gemm(sb, aH, aL, bH, bL, HIDDEN / 32, tid, acc);

    int l  = tid & 31;
    int wm = (tid >> 5) & 3;
    int wn = (tid >> 5) >> 2;
    int g  = l >> 2;
    int t  = l & 3;
    const float* be = b2 + (size_t)e * D_MODEL + n0b + wn * 64;

    #pragma unroll
    for (int mf = 0; mf < 2; mf++)
        #pragma unroll
        for (int rr = 0; rr < 2; rr++) {
            int m = wm * 32 + mf * 16 + g + rr * 8;
            if (m < rows) {
                int tok = g_perm[row0 + m];
                float w = g_wsel[tok];
                float* ob = out + (size_t)tok * D_MODEL + n0b + wn * 64;
                #pragma unroll
                for (int nb = 0; nb < 8; nb++) {
                    int nc = nb * 8 + t * 2;
                    float2 bb = *(const float2*)(be + nc);
                    float2 v;
                    v.x = w * (acc[mf][nb][rr * 2 + 0] + bb.x);
                    v.y = w * (acc[mf][nb][rr * 2 + 1] + bb.y);
                    *(float2*)(ob + nc) = v;
                }
            }
        }
}

// ---------------- kernel 7: aux loss (tiny, reads g_imp) ----------------
__global__ void aux_kernel(float* __restrict__ out, int T) {
    if (threadIdx.x == 0 && blockIdx.x == 0) {
        float s = 0.0f;
        #pragma unroll
        for (int e = 0; e < N_EXP; e++) {
            float im = (float)(g_imp[e] / (double)T);
            float d = im - 0.125f;
            s += d * d;
        }
        out[(size_t)T * D_MODEL] = s * (1.0f / 8.0f);
    }
}

// ---------------- launch ----------------
extern "C" void kernel_launch(void* const* d_in, const int* in_sizes, int n_in,
                              void* d_out, int out_size)
{
    const float* x  = (const float*)d_in[0];
    const float* u  = (const float*)d_in[1];
    const float* rw = (const float*)d_in[2];
    const float* rb = (const float*)d_in[3];
    const float* w1 = (const float*)d_in[4];
    const float* b1 = (const float*)d_in[5];
    const float* w2 = (const float*)d_in[6];
    const float* b2 = (const float*)d_in[7];
    float* out = (float*)d_out;

    int T = in_sizes[0] / D_MODEL;   // 8192

    cudaFuncSetAttribute(ffn1_kernel, cudaFuncAttributeMaxDynamicSharedMemorySize, SMEM_TOT);
    cudaFuncSetAttribute(ffn2_kernel, cudaFuncAttributeMaxDynamicSharedMemorySize, SMEM_TOT);

    init_kernel<<<1, 32>>>();
    router_kernel<<<T / 8, 256>>>(x, u, rw, rb, T);
    scatter_kernel<<<1, 1024>>>(T);
    convx_kernel<<<(T * 128 + 255) / 256, 256>>>(x, T);

    dim3 cb(32, 8);
    convT_kernel<D_MODEL, HIDDEN, 1><<<dim3(HIDDEN / 32, D_MODEL / 32, N_EXP), cb>>>(w1);
    convT_kernel<HIDDEN, D_MODEL, 2><<<dim3(D_MODEL / 32, HIDDEN / 32, N_EXP), cb>>>(w2);

    int max_tiles = T / TILE_M + N_EXP;
    ffn1_kernel<<<dim3(HIDDEN / 128, max_tiles), 256, SMEM_TOT>>>(b1);
    ffn2_kernel<<<dim3(D_MODEL / 128, max_tiles), 256, SMEM_TOT>>>(b2, out);

    aux_kernel<<<1, 32>>>(out, T);
}

// round 15
// speedup vs baseline: 1.5352x; 1.5352x over previous
#include <cuda_runtime.h>
#include <cuda_bf16.h>
#include <math.h>

#define D_MODEL 512
#define N_EXP   8
#define HIDDEN  2048
#define T_MAX   8192
#define TILE_M  128
#define MAX_TILES (T_MAX/TILE_M + N_EXP)

typedef unsigned int u32;
typedef unsigned short u16;

// swizzled smem: each region = 128 logical rows x 32 u16 (64B), packed as
// 64 phys rows x 128B with XOR swizzle; region = 8192 B, stage = 4 regions.
#define R_AH 0
#define R_AL 8192
#define R_BH 16384
#define R_BL 24576
#define BUF_B 32768
#define NSTAGE 3
#define SMEM_TOT (NSTAGE * BUF_B)   // 98304 B

// ---------------- scratch (device globals, no allocation) ----------------
__device__ __align__(16) u16 g_xhi[(size_t)T_MAX * D_MODEL];
__device__ __align__(16) u16 g_xlo[(size_t)T_MAX * D_MODEL];
__device__ __align__(16) u16 g_w1hi[(size_t)N_EXP * HIDDEN * D_MODEL]; // [E][H][D] transposed
__device__ __align__(16) u16 g_w1lo[(size_t)N_EXP * HIDDEN * D_MODEL];
__device__ __align__(16) u16 g_w2hi[(size_t)N_EXP * D_MODEL * HIDDEN]; // [E][D][H] transposed
__device__ __align__(16) u16 g_w2lo[(size_t)N_EXP * D_MODEL * HIDDEN];
__device__ __align__(16) u16 g_hhi[(size_t)T_MAX * HIDDEN];
__device__ __align__(16) u16 g_hlo[(size_t)T_MAX * HIDDEN];
__device__ int    g_perm[T_MAX];
__device__ int    g_tok_exp[T_MAX];
__device__ float  g_wsel[T_MAX];
__device__ double g_imp[N_EXP];
__device__ int    g_tile_exp[MAX_TILES];
__device__ int    g_tile_row0[MAX_TILES];
__device__ int    g_tile_rows[MAX_TILES];
__device__ int    g_ntiles;

__device__ __forceinline__ float gelu_exact(float v) {
    return 0.5f * v * (1.0f + erff(v * 0.70710678118654752440f));
}
__device__ __forceinline__ u32 smem_u32(const void* p) {
    u32 a;
    asm("{ .reg .u64 t; cvta.to.shared.u64 t, %1; cvt.u32.u64 %0, t; }" : "=r"(a) : "l"(p));
    return a;
}
// swizzle: logical (row r in 0..127, 16B unit c in 0..3) -> byte offset in region
__device__ __forceinline__ u32 swz(u32 r, u32 c) {
    return ((r >> 1) << 7) | (((((r & 1) << 2) | c) ^ ((r >> 1) & 7)) << 4);
}

// ---- portable PTX (sm_80+): cp.async, ldmatrix, mma ----
#define CP16(d, s)  asm volatile("cp.async.cg.shared.global [%0], [%1], 16;" :: "r"(d), "l"(s))
#define CPCOMMIT()  asm volatile("cp.async.commit_group;" ::: "memory")
#define CPWAIT1()   asm volatile("cp.async.wait_group 1;" ::: "memory")
#define CPWAIT0()   asm volatile("cp.async.wait_group 0;" ::: "memory")

#define LDM4(r, a) \
    asm volatile("ldmatrix.sync.aligned.m8n8.x4.shared.b16 {%0,%1,%2,%3}, [%4];" \
        : "=r"((r)[0]), "=r"((r)[1]), "=r"((r)[2]), "=r"((r)[3]) : "r"(a))

#define MMA(ac, a0, a1, a2, a3, b0, b1) \
    asm volatile("mma.sync.aligned.m16n8k16.row.col.f32.bf16.bf16.f32 " \
        "{%0,%1,%2,%3},{%4,%5,%6,%7},{%8,%9},{%0,%1,%2,%3};" \
        : "+f"((ac)[0]), "+f"((ac)[1]), "+f"((ac)[2]), "+f"((ac)[3]) \
        : "r"(a0), "r"(a1), "r"(a2), "r"(a3), "r"(b0), "r"(b1))

// ---------------- kernel 0 ----------------
__global__ void init_kernel() {
    if (threadIdx.x < N_EXP) g_imp[threadIdx.x] = 0.0;
}

// ---------------- kernel 1: router (proven: shared float + global double atomics) ----
__global__ void __launch_bounds__(256) router_kernel(
    const float* __restrict__ x, const float* __restrict__ u,
    const float* __restrict__ rw, const float* __restrict__ rb, int T)
{
    __shared__ float s_imp[N_EXP];
    if (threadIdx.x < N_EXP) s_imp[threadIdx.x] = 0.0f;
    __syncthreads();

    int t    = blockIdx.x * 8 + (threadIdx.x >> 5);
    int lane = threadIdx.x & 31;

    if (t < T) {
        float acc[8];
        #pragma unroll
        for (int e = 0; e < 8; e++) acc[e] = 0.0f;
        const float* xr = x + (size_t)t * D_MODEL;
        for (int k = lane; k < D_MODEL; k += 32) {
            float xv = xr[k];
            float4 wa = *(const float4*)(rw + k * 8);
            float4 wb = *(const float4*)(rw + k * 8 + 4);
            acc[0] += xv * wa.x; acc[1] += xv * wa.y;
            acc[2] += xv * wa.z; acc[3] += xv * wa.w;
            acc[4] += xv * wb.x; acc[5] += xv * wb.y;
            acc[6] += xv * wb.z; acc[7] += xv * wb.w;
        }
        #pragma unroll
        for (int e = 0; e < 8; e++) {
            #pragma unroll
            for (int off = 16; off > 0; off >>= 1)
                acc[e] += __shfl_down_sync(0xffffffffu, acc[e], off);
        }
        if (lane == 0) {
            float logits[8];
            #pragma unroll
            for (int e = 0; e < 8; e++) logits[e] = acc[e] + rb[e];
            float m = logits[0];
            #pragma unroll
            for (int e = 1; e < 8; e++) m = fmaxf(m, logits[e]);
            float p[8]; float se = 0.0f;
            #pragma unroll
            for (int e = 0; e < 8; e++) { p[e] = expf(logits[e] - m); se += p[e]; }
            float inv = 1.0f / se;
            #pragma unroll
            for (int e = 0; e < 8; e++) atomicAdd(&s_imp[e], p[e] * inv);

            const float* ur = u + (size_t)t * 8;
            float z[8]; int best = 0; float zb = -1e30f;
            #pragma unroll
            for (int e = 0; e < 8; e++) {
                float g = -logf(-logf(ur[e]) + 1e-10f);
                z[e] = logits[e] + g;
                if (z[e] > zb) { zb = z[e]; best = e; }
            }
            float s2 = 0.0f;
            #pragma unroll
            for (int e = 0; e < 8; e++) s2 += expf(z[e] - zb);
            float y = 1.0f / s2;
            g_tok_exp[t] = best;
            g_wsel[t]    = (1.0f - y) + y;
        }
    }
    __syncthreads();
    if (threadIdx.x < N_EXP)
        atomicAdd(&g_imp[threadIdx.x], (double)s_imp[threadIdx.x]);
}

// ---------------- kernel 2: scatter + tiles ----------------
__global__ void scatter_kernel(int T) {
    __shared__ int s_cnt[N_EXP];
    __shared__ int s_run[N_EXP];
    int tid = threadIdx.x;
    if (tid < N_EXP) s_cnt[tid] = 0;
    __syncthreads();
    for (int t = tid; t < T; t += blockDim.x)
        atomicAdd(&s_cnt[g_tok_exp[t]], 1);
    __syncthreads();
    if (tid == 0) {
        int off = 0, nt = 0;
        for (int e = 0; e < N_EXP; e++) {
            int c = s_cnt[e];
            s_run[e] = off;
            for (int m = 0; m < c; m += TILE_M) {
                g_tile_exp[nt]  = e;
                g_tile_row0[nt] = off + m;
                g_tile_rows[nt] = min(TILE_M, c - m);
                nt++;
            }
            off += c;
        }
        g_ntiles = nt;
    }
    __syncthreads();
    for (int t = tid; t < T; t += blockDim.x) {
        int pos = atomicAdd(&s_run[g_tok_exp[t]], 1);
        g_perm[pos] = t;
    }
}

// ---------------- kernel 3: gather + hi/lo convert x (perm order) ----------------
__global__ void __launch_bounds__(256) convx_kernel(const float* __restrict__ x, int T) {
    int idx = blockIdx.x * 256 + threadIdx.x;
    if (idx >= T * (D_MODEL / 4)) return;
    int row  = idx >> 7;
    int col4 = idx & 127;
    int tok  = g_perm[row];
    float4 v = ((const float4*)x)[(size_t)tok * 128 + col4];
    __nv_bfloat16 h0 = __float2bfloat16(v.x), h1 = __float2bfloat16(v.y);
    __nv_bfloat16 h2 = __float2bfloat16(v.z), h3 = __float2bfloat16(v.w);
    ushort4 H, L;
    H.x = __bfloat16_as_ushort(h0); H.y = __bfloat16_as_ushort(h1);
    H.z = __bfloat16_as_ushort(h2); H.w = __bfloat16_as_ushort(h3);
    L.x = __bfloat16_as_ushort(__float2bfloat16(v.x - __bfloat162float(h0)));
    L.y = __bfloat16_as_ushort(__float2bfloat16(v.y - __bfloat162float(h1)));
    L.z = __bfloat16_as_ushort(__float2bfloat16(v.z - __bfloat162float(h2)));
    L.w = __bfloat16_as_ushort(__float2bfloat16(v.w - __bfloat162float(h3)));
    size_t o = (size_t)row * D_MODEL + col4 * 4;
    *(ushort4*)(g_xhi + o) = H;
    *(ushort4*)(g_xlo + o) = L;
}

// ---------------- kernel 4: transpose + hi/lo convert weights ----------------
// Destination device globals referenced INSIDE the kernel.
template<int R, int C, int WHICH>
__global__ void __launch_bounds__(256) convT_kernel(const float* __restrict__ src)
{
    __shared__ float tile[32][33];
    int e  = blockIdx.z;
    int c0 = blockIdx.x * 32, r0 = blockIdx.y * 32;
    int tx = threadIdx.x, ty = threadIdx.y;
    #pragma unroll
    for (int i = 0; i < 4; i++) {
        int r = r0 + ty + i * 8;
        tile[ty + i * 8][tx] = src[((size_t)e * R + r) * C + c0 + tx];
    }
    __syncthreads();
    u16* dhi = (WHICH == 1) ? g_w1hi : g_w2hi;
    u16* dlo = (WHICH == 1) ? g_w1lo : g_w2lo;
    #pragma unroll
    for (int i = 0; i < 4; i++) {
        int c = c0 + ty + i * 8;
        int r = r0 + tx;
        float v = tile[tx][ty + i * 8];
        __nv_bfloat16 h = __float2bfloat16(v);
        float lo = v - __bfloat162float(h);
        size_t o = ((size_t)e * C + c) * R + r;
        dhi[o] = __bfloat16_as_ushort(h);
        dlo[o] = __bfloat16_as_ushort(__float2bfloat16(lo));
    }
}

// ---------------- GEMM mainloop: 3-stage cp.async, swizzled smem, 1 sync/chunk ---------
// CTA tile 128x128, 8 warps (4m x 2n), warp tile 32x64, K-chunk 32.
__device__ __forceinline__ void run_gemm(
    u32 sb, const u16* aH, const u16* aL, const u16* bH, const u16* bL,
    int NC, int tid, float acc[2][8][4])
{
    int l  = tid & 31;
    int wm = (tid >> 5) & 3;
    int wn = (tid >> 5) >> 2;

    u32 r_st = (u32)(tid >> 1);
    u32 u0   = (u32)(tid & 1) * 2;
    u32 d0 = swz(r_st, u0);
    u32 d1 = swz(r_st, u0 + 1);

    u32 r_a = (u32)(wm * 32 + (l & 7) + ((l & 8) ? 8 : 0));
    u32 ca  = (l & 16) ? 1u : 0u;
    u32 r_b = (u32)(wn * 64 + (l & 7) + ((l & 16) ? 8 : 0));
    u32 cb  = (l & 8) ? 1u : 0u;

    #define ISSUE(c, st) do { \
        u32 base = sb + (u32)(st) * BUF_B; \
        const u16* s_; \
        s_ = aH + (size_t)(c) * 32; CP16(base + R_AH + d0, s_); CP16(base + R_AH + d1, s_ + 8); \
        s_ = aL + (size_t)(c) * 32; CP16(base + R_AL + d0, s_); CP16(base + R_AL + d1, s_ + 8); \
        s_ = bH + (size_t)(c) * 32; CP16(base + R_BH + d0, s_); CP16(base + R_BH + d1, s_ + 8); \
        s_ = bL + (size_t)(c) * 32; CP16(base + R_BL + d0, s_); CP16(base + R_BL + d1, s_ + 8); \
        CPCOMMIT(); \
    } while (0)

    ISSUE(0, 0);
    if (NC > 1) ISSUE(1, 1);

    int st  = 0;
    int ist = 2;
    for (int c = 0; c < NC; c++) {
        if (c + 1 < NC) { CPWAIT1(); } else { CPWAIT0(); }
        __syncthreads();
        u32 buf = sb + (u32)st * BUF_B;

        #pragma unroll
        for (int kk = 0; kk < 2; kk++) {
            u32 cc = (u32)kk * 2;
            u32 ah0[4], ah1[4], al0[4], al1[4];
            LDM4(ah0, buf + R_AH + swz(r_a,      cc + ca));
            LDM4(ah1, buf + R_AH + swz(r_a + 16, cc + ca));
            LDM4(al0, buf + R_AL + swz(r_a,      cc + ca));
            LDM4(al1, buf + R_AL + swz(r_a + 16, cc + ca));

            #pragma unroll
            for (int p = 0; p < 4; p++) {
                u32 bh[4], bl[4];
                u32 so = swz(r_b + (u32)p * 16, cc + cb);
                LDM4(bh, buf + R_BH + so);
                LDM4(bl, buf + R_BL + so);
                int n0 = p * 2;
                MMA(acc[0][n0],   ah0[0], ah0[1], ah0[2], ah0[3], bh[0], bh[1]);
                MMA(acc[0][n0],   ah0[0], ah0[1], ah0[2], ah0[3], bl[0], bl[1]);
                MMA(acc[0][n0],   al0[0], al0[1], al0[2], al0[3], bh[0], bh[1]);
                MMA(acc[0][n0+1], ah0[0], ah0[1], ah0[2], ah0[3], bh[2], bh[3]);
                MMA(acc[0][n0+1], ah0[0], ah0[1], ah0[2], ah0[3], bl[2], bl[3]);
                MMA(acc[0][n0+1], al0[0], al0[1], al0[2], al0[3], bh[2], bh[3]);
                MMA(acc[1][n0],   ah1[0], ah1[1], ah1[2], ah1[3], bh[0], bh[1]);
                MMA(acc[1][n0],   ah1[0], ah1[1], ah1[2], ah1[3], bl[0], bl[1]);
                MMA(acc[1][n0],   al1[0], al1[1], al1[2], al1[3], bh[0], bh[1]);
                MMA(acc[1][n0+1], ah1[0], ah1[1], ah1[2], ah1[3], bh[2], bh[3]);
                MMA(acc[1][n0+1], ah1[0], ah1[1], ah1[2], ah1[3], bl[2], bl[3]);
                MMA(acc[1][n0+1], al1[0], al1[1], al1[2], al1[3], bh[2], bh[3]);
            }
        }
        if (c + 2 < NC) ISSUE(c + 2, ist);
        st  = (st  == 2) ? 0 : st  + 1;
        ist = (ist == 2) ? 0 : ist + 1;
    }
    #undef ISSUE
}

// ---------------- kernel 5: FFN1 ----------------
__global__ void __launch_bounds__(256, 2) ffn1_kernel(const float* __restrict__ b1)
{
    int tile = blockIdx.y;
    if (tile >= g_ntiles) return;
    int e    = g_tile_exp[tile];
    int row0 = g_tile_row0[tile];
    int rows = g_tile_rows[tile];
    int n0b  = blockIdx.x * 128;

    extern __shared__ u16 smem_dyn[];
    u32 sb  = smem_u32(smem_dyn);
    int tid = threadIdx.x;
    int seg = (tid & 1) * 16;

    int arow = row0 + min(tid >> 1, rows - 1);
    const u16* aH = g_xhi + (size_t)arow * D_MODEL + seg;
    const u16* aL = g_xlo + (size_t)arow * D_MODEL + seg;
    size_t boff = ((size_t)e * HIDDEN + n0b + (tid >> 1)) * D_MODEL + seg;
    const u16* bH = g_w1hi + boff;
    const u16* bL = g_w1lo + boff;

    float acc[2][8][4];
    #pragma unroll
    for (int i = 0; i < 2; i++)
        #pragma unroll
        for (int j = 0; j < 8; j++)
            #pragma unroll
            for (int q = 0; q < 4; q++) acc[i][j][q] = 0.0f;

    run_gemm(sb, aH, aL, bH, bL, D_MODEL / 32, tid, acc);

    int l  = tid & 31;
    int wm = (tid >> 5) & 3;
    int wn = (tid >> 5) >> 2;
    int g  = l >> 2;
    int t  = l & 3;
    const float* be = b1 + (size_t)e * HIDDEN + n0b + wn * 64;

    #pragma unroll
    for (int mf = 0; mf < 2; mf++)
        #pragma unroll
        for (int rr = 0; rr < 2; rr++) {
            int m = wm * 32 + mf * 16 + g + rr * 8;
            if (m < rows) {
                size_t ro = (size_t)(row0 + m) * HIDDEN + n0b + wn * 64;
                #pragma unroll
                for (int nb = 0; nb < 8; nb++) {
                    int nc = nb * 8 + t * 2;
                    float2 bb = *(const float2*)(be + nc);
                    float f0 = gelu_exact(acc[mf][nb][rr * 2 + 0] + bb.x);
                    float f1 = gelu_exact(acc[mf][nb][rr * 2 + 1] + bb.y);
                    __nv_bfloat16 h0 = __float2bfloat16(f0);
                    __nv_bfloat16 h1 = __float2bfloat16(f1);
                    u32 hp = (u32)__bfloat16_as_ushort(h0) | ((u32)__bfloat16_as_ushort(h1) << 16);
                    u16 l0 = __bfloat16_as_ushort(__float2bfloat16(f0 - __bfloat162float(h0)));
                    u16 l1 = __bfloat16_as_ushort(__float2bfloat16(f1 - __bfloat162float(h1)));
                    u32 lp = (u32)l0 | ((u32)l1 << 16);
                    *(u32*)(g_hhi + ro + nc) = hp;
                    *(u32*)(g_hlo + ro + nc) = lp;
                }
            }
        }
}

// ---------------- kernel 6: FFN2 ----------------
__global__ void __launch_bounds__(256, 2) ffn2_kernel(
    const float* __restrict__ b2, float* __restrict__ out)
{
    int tile = blockIdx.y;
    if (tile >= g_ntiles) return;
    int e    = g_tile_exp[tile];
    int row0 = g_tile_row0[tile];
    int rows = g_tile_rows[tile];
    int n0b  = blockIdx.x * 128;

    extern __shared__ u16 smem_dyn[];
    u32 sb  = smem_u32(smem_dyn);
    int tid = threadIdx.x;
    int seg = (tid & 1) * 16;

    int arow = row0 + min(tid >> 1, rows - 1);
    const u16* aH = g_hhi + (size_t)arow * HIDDEN + seg;
    const u16* aL = g_hlo + (size_t)arow * HIDDEN + seg;
    size_t boff = ((size_t)e * D_MODEL + n0b + (tid >> 1)) * HIDDEN + seg;
    const u16* bH = g_w2hi + boff;
    const u16* bL = g_w2lo + boff;

    float acc[2][8][4];
    #pragma unroll
    for (int i = 0; i < 2; i++)
        #pragma unroll
        for (int j = 0; j < 8; j++)
            #pragma unroll
            for (int q = 0; q < 4; q++) acc[i][j][q] = 0.0f;

    run_gemm(sb, aH, aL, bH, bL, HIDDEN / 32, tid, acc);

    int l  = tid & 31;
    int wm = (tid >> 5) & 3;
    int wn = (tid >> 5) >> 2;
    int g  = l >> 2;
    int t  = l & 3;
    const float* be = b2 + (size_t)e * D_MODEL + n0b + wn * 64;

    #pragma unroll
    for (int mf = 0; mf < 2; mf++)
        #pragma unroll
        for (int rr = 0; rr < 2; rr++) {
            int m = wm * 32 + mf * 16 + g + rr * 8;
            if (m < rows) {
                int tok = g_perm[row0 + m];
                float w = g_wsel[tok];
                float* ob = out + (size_t)tok * D_MODEL + n0b + wn * 64;
                #pragma unroll
                for (int nb = 0; nb < 8; nb++) {
                    int nc = nb * 8 + t * 2;
                    float2 bb = *(const float2*)(be + nc);
                    float2 v;
                    v.x = w * (acc[mf][nb][rr * 2 + 0] + bb.x);
                    v.y = w * (acc[mf][nb][rr * 2 + 1] + bb.y);
                    *(float2*)(ob + nc) = v;
                }
            }
        }
}

// ---------------- kernel 7: aux loss (tiny, reads g_imp) ----------------
__global__ void aux_kernel(float* __restrict__ out, int T) {
    if (threadIdx.x == 0 && blockIdx.x == 0) {
        float s = 0.0f;
        #pragma unroll
        for (int e = 0; e < N_EXP; e++) {
            float im = (float)(g_imp[e] / (double)T);
            float d = im - 0.125f;
            s += d * d;
        }
        out[(size_t)T * D_MODEL] = s * (1.0f / 8.0f);
    }
}

// ---------------- launch ----------------
extern "C" void kernel_launch(void* const* d_in, const int* in_sizes, int n_in,
                              void* d_out, int out_size)
{
    const float* x  = (const float*)d_in[0];
    const float* u  = (const float*)d_in[1];
    const float* rw = (const float*)d_in[2];
    const float* rb = (const float*)d_in[3];
    const float* w1 = (const float*)d_in[4];
    const float* b1 = (const float*)d_in[5];
    const float* w2 = (const float*)d_in[6];
    const float* b2 = (const float*)d_in[7];
    float* out = (float*)d_out;

    int T = in_sizes[0] / D_MODEL;   // 8192

    cudaFuncSetAttribute(ffn1_kernel, cudaFuncAttributeMaxDynamicSharedMemorySize, SMEM_TOT);
    cudaFuncSetAttribute(ffn2_kernel, cudaFuncAttributeMaxDynamicSharedMemorySize, SMEM_TOT);

    init_kernel<<<1, 32>>>();
    router_kernel<<<T / 8, 256>>>(x, u, rw, rb, T);
    scatter_kernel<<<1, 1024>>>(T);
    convx_kernel<<<(T * 128 + 255) / 256, 256>>>(x, T);

    dim3 cb(32, 8);
    convT_kernel<D_MODEL, HIDDEN, 1><<<dim3(HIDDEN / 32, D_MODEL / 32, N_EXP), cb>>>(w1);
    convT_kernel<HIDDEN, D_MODEL, 2><<<dim3(D_MODEL / 32, HIDDEN / 32, N_EXP), cb>>>(w2);

    int max_tiles = T / TILE_M + N_EXP;
    ffn1_kernel<<<dim3(HIDDEN / 128, max_tiles), 256, SMEM_TOT>>>(b1);
    ffn2_kernel<<<dim3(D_MODEL / 128, max_tiles), 256, SMEM_TOT>>>(b2, out);

    aux_kernel<<<1, 32>>>(out, T);
}

// round 16
// speedup vs baseline: 2.0296x; 1.3221x over previous
#include <cuda_runtime.h>
#include <cuda_fp16.h>
#include <math.h>

#define D_MODEL 512
#define N_EXP   8
#define HIDDEN  2048
#define T_MAX   8192
#define TILE_M  128
#define MAX_TILES (T_MAX/TILE_M + N_EXP)

typedef unsigned int u32;
typedef unsigned short u16;

// swizzled smem: region = 128 logical rows x 32 fp16 (64B), packed as
// 64 phys rows x 128B with XOR swizzle; region = 8192 B, stage = 3 regions.
#define R_A  0
#define R_BH 8192
#define R_BL 16384
#define BUF_B 24576
#define NSTAGE 3
#define SMEM_TOT (NSTAGE * BUF_B)   // 73728 B

// ---------------- scratch (device globals, no allocation) ----------------
__device__ __align__(16) u16 g_xh[(size_t)T_MAX * D_MODEL];            // fp16 x (rounded)
__device__ __align__(16) u16 g_w1hi[(size_t)N_EXP * HIDDEN * D_MODEL]; // [E][H][D] transposed fp16 hi
__device__ __align__(16) u16 g_w1lo[(size_t)N_EXP * HIDDEN * D_MODEL]; // fp16 residual
__device__ __align__(16) u16 g_w2hi[(size_t)N_EXP * D_MODEL * HIDDEN]; // [E][D][H] transposed
__device__ __align__(16) u16 g_w2lo[(size_t)N_EXP * D_MODEL * HIDDEN];
__device__ __align__(16) u16 g_hh[(size_t)T_MAX * HIDDEN];             // fp16 h (rounded)
__device__ int    g_perm[T_MAX];
__device__ int    g_tok_exp[T_MAX];
__device__ float  g_wsel[T_MAX];
__device__ double g_imp[N_EXP];
__device__ int    g_tile_exp[MAX_TILES];
__device__ int    g_tile_row0[MAX_TILES];
__device__ int    g_tile_rows[MAX_TILES];
__device__ int    g_ntiles;

__device__ __forceinline__ float gelu_exact(float v) {
    return 0.5f * v * (1.0f + erff(v * 0.70710678118654752440f));
}
__device__ __forceinline__ u32 smem_u32(const void* p) {
    u32 a;
    asm("{ .reg .u64 t; cvta.to.shared.u64 t, %1; cvt.u32.u64 %0, t; }" : "=r"(a) : "l"(p));
    return a;
}
// swizzle: logical (row r in 0..127, 16B unit c in 0..3) -> byte offset in region
__device__ __forceinline__ u32 swz(u32 r, u32 c) {
    return ((r >> 1) << 7) | (((((r & 1) << 2) | c) ^ ((r >> 1) & 7)) << 4);
}

// ---- portable PTX (sm_80+): cp.async, ldmatrix, mma ----
#define CP16(d, s)  asm volatile("cp.async.cg.shared.global [%0], [%1], 16;" :: "r"(d), "l"(s))
#define CPCOMMIT()  asm volatile("cp.async.commit_group;" ::: "memory")
#define CPWAIT1()   asm volatile("cp.async.wait_group 1;" ::: "memory")
#define CPWAIT0()   asm volatile("cp.async.wait_group 0;" ::: "memory")

#define LDM4(r, a) \
    asm volatile("ldmatrix.sync.aligned.m8n8.x4.shared.b16 {%0,%1,%2,%3}, [%4];" \
        : "=r"((r)[0]), "=r"((r)[1]), "=r"((r)[2]), "=r"((r)[3]) : "r"(a))

#define MMA(ac, a0, a1, a2, a3, b0, b1) \
    asm volatile("mma.sync.aligned.m16n8k16.row.col.f32.f16.f16.f32 " \
        "{%0,%1,%2,%3},{%4,%5,%6,%7},{%8,%9},{%0,%1,%2,%3};" \
        : "+f"((ac)[0]), "+f"((ac)[1]), "+f"((ac)[2]), "+f"((ac)[3]) \
        : "r"(a0), "r"(a1), "r"(a2), "r"(a3), "r"(b0), "r"(b1))

// ---------------- kernel 0 ----------------
__global__ void init_kernel() {
    if (threadIdx.x < N_EXP) g_imp[threadIdx.x] = 0.0;
}

// ---------------- kernel 1: router (proven) ----------------
__global__ void __launch_bounds__(256) router_kernel(
    const float* __restrict__ x, const float* __restrict__ u,
    const float* __restrict__ rw, const float* __restrict__ rb, int T)
{
    __shared__ float s_imp[N_EXP];
    if (threadIdx.x < N_EXP) s_imp[threadIdx.x] = 0.0f;
    __syncthreads();

    int t    = blockIdx.x * 8 + (threadIdx.x >> 5);
    int lane = threadIdx.x & 31;

    if (t < T) {
        float acc[8];
        #pragma unroll
        for (int e = 0; e < 8; e++) acc[e] = 0.0f;
        const float* xr = x + (size_t)t * D_MODEL;
        for (int k = lane; k < D_MODEL; k += 32) {
            float xv = xr[k];
            float4 wa = *(const float4*)(rw + k * 8);
            float4 wb = *(const float4*)(rw + k * 8 + 4);
            acc[0] += xv * wa.x; acc[1] += xv * wa.y;
            acc[2] += xv * wa.z; acc[3] += xv * wa.w;
            acc[4] += xv * wb.x; acc[5] += xv * wb.y;
            acc[6] += xv * wb.z; acc[7] += xv * wb.w;
        }
        #pragma unroll
        for (int e = 0; e < 8; e++) {
            #pragma unroll
            for (int off = 16; off > 0; off >>= 1)
                acc[e] += __shfl_down_sync(0xffffffffu, acc[e], off);
        }
        if (lane == 0) {
            float logits[8];
            #pragma unroll
            for (int e = 0; e < 8; e++) logits[e] = acc[e] + rb[e];
            float m = logits[0];
            #pragma unroll
            for (int e = 1; e < 8; e++) m = fmaxf(m, logits[e]);
            float p[8]; float se = 0.0f;
            #pragma unroll
            for (int e = 0; e < 8; e++) { p[e] = expf(logits[e] - m); se += p[e]; }
            float inv = 1.0f / se;
            #pragma unroll
            for (int e = 0; e < 8; e++) atomicAdd(&s_imp[e], p[e] * inv);

            const float* ur = u + (size_t)t * 8;
            float z[8]; int best = 0; float zb = -1e30f;
            #pragma unroll
            for (int e = 0; e < 8; e++) {
                float g = -logf(-logf(ur[e]) + 1e-10f);
                z[e] = logits[e] + g;
                if (z[e] > zb) { zb = z[e]; best = e; }
            }
            float s2 = 0.0f;
            #pragma unroll
            for (int e = 0; e < 8; e++) s2 += expf(z[e] - zb);
            float y = 1.0f / s2;
            g_tok_exp[t] = best;
            g_wsel[t]    = (1.0f - y) + y;
        }
    }
    __syncthreads();
    if (threadIdx.x < N_EXP)
        atomicAdd(&g_imp[threadIdx.x], (double)s_imp[threadIdx.x]);
}

// ---------------- kernel 2: scatter + tiles (proven) ----------------
__global__ void scatter_kernel(int T) {
    __shared__ int s_cnt[N_EXP];
    __shared__ int s_run[N_EXP];
    int tid = threadIdx.x;
    if (tid < N_EXP) s_cnt[tid] = 0;
    __syncthreads();
    for (int t = tid; t < T; t += blockDim.x)
        atomicAdd(&s_cnt[g_tok_exp[t]], 1);
    __syncthreads();
    if (tid == 0) {
        int off = 0, nt = 0;
        for (int e = 0; e < N_EXP; e++) {
            int c = s_cnt[e];
            s_run[e] = off;
            for (int m = 0; m < c; m += TILE_M) {
                g_tile_exp[nt]  = e;
                g_tile_row0[nt] = off + m;
                g_tile_rows[nt] = min(TILE_M, c - m);
                nt++;
            }
            off += c;
        }
        g_ntiles = nt;
    }
    __syncthreads();
    for (int t = tid; t < T; t += blockDim.x) {
        int pos = atomicAdd(&s_run[g_tok_exp[t]], 1);
        g_perm[pos] = t;
    }
}

// ---------------- kernel 3: gather + fp16 round x (perm order) ----------------
__global__ void __launch_bounds__(256) convx_kernel(const float* __restrict__ x, int T) {
    int idx = blockIdx.x * 256 + threadIdx.x;
    if (idx >= T * (D_MODEL / 4)) return;
    int row  = idx >> 7;
    int col4 = idx & 127;
    int tok  = g_perm[row];
    float4 v = ((const float4*)x)[(size_t)tok * 128 + col4];
    ushort4 H;
    H.x = __half_as_ushort(__float2half(v.x));
    H.y = __half_as_ushort(__float2half(v.y));
    H.z = __half_as_ushort(__float2half(v.z));
    H.w = __half_as_ushort(__float2half(v.w));
    *(ushort4*)(g_xh + (size_t)row * D_MODEL + col4 * 4) = H;
}

// ---------------- kernel 4: transpose + fp16 hi/lo convert weights ----------------
template<int R, int C, int WHICH>
__global__ void __launch_bounds__(256) convT_kernel(const float* __restrict__ src)
{
    __shared__ float tile[32][33];
    int e  = blockIdx.z;
    int c0 = blockIdx.x * 32, r0 = blockIdx.y * 32;
    int tx = threadIdx.x, ty = threadIdx.y;
    #pragma unroll
    for (int i = 0; i < 4; i++) {
        int r = r0 + ty + i * 8;
        tile[ty + i * 8][tx] = src[((size_t)e * R + r) * C + c0 + tx];
    }
    __syncthreads();
    u16* dhi = (WHICH == 1) ? g_w1hi : g_w2hi;
    u16* dlo = (WHICH == 1) ? g_w1lo : g_w2lo;
    #pragma unroll
    for (int i = 0; i < 4; i++) {
        int c = c0 + ty + i * 8;
        int r = r0 + tx;
        float v = tile[tx][ty + i * 8];
        __half h = __float2half(v);
        float lo = v - __half2float(h);
        size_t o = ((size_t)e * C + c) * R + r;
        dhi[o] = __half_as_ushort(h);
        dlo[o] = __half_as_ushort(__float2half(lo));
    }
}

// ---------------- GEMM mainloop: 3-stage cp.async, swizzled, fp16 2-term ---------
// CTA tile 128x128, 8 warps (4m x 2n), warp tile 32x64, K-chunk 32.
__device__ __forceinline__ void run_gemm(
    u32 sb, const u16* aP, const u16* bH, const u16* bL,
    int NC, int tid, float acc[2][8][4])
{
    int l  = tid & 31;
    int wm = (tid >> 5) & 3;
    int wn = (tid >> 5) >> 2;

    u32 r_st = (u32)(tid >> 1);
    u32 u0   = (u32)(tid & 1) * 2;
    u32 d0 = swz(r_st, u0);
    u32 d1 = swz(r_st, u0 + 1);

    u32 r_a = (u32)(wm * 32 + (l & 7) + ((l & 8) ? 8 : 0));
    u32 ca  = (l & 16) ? 1u : 0u;
    u32 r_b = (u32)(wn * 64 + (l & 7) + ((l & 16) ? 8 : 0));
    u32 cb  = (l & 8) ? 1u : 0u;

    #define ISSUE(c, st) do { \
        u32 base = sb + (u32)(st) * BUF_B; \
        const u16* s_; \
        s_ = aP + (size_t)(c) * 32; CP16(base + R_A  + d0, s_); CP16(base + R_A  + d1, s_ + 8); \
        s_ = bH + (size_t)(c) * 32; CP16(base + R_BH + d0, s_); CP16(base + R_BH + d1, s_ + 8); \
        s_ = bL + (size_t)(c) * 32; CP16(base + R_BL + d0, s_); CP16(base + R_BL + d1, s_ + 8); \
        CPCOMMIT(); \
    } while (0)

    ISSUE(0, 0);
    if (NC > 1) ISSUE(1, 1);

    int st  = 0;
    int ist = 2;
    for (int c = 0; c < NC; c++) {
        if (c + 1 < NC) { CPWAIT1(); } else { CPWAIT0(); }
        __syncthreads();
        u32 buf = sb + (u32)st * BUF_B;

        #pragma unroll
        for (int kk = 0; kk < 2; kk++) {
            u32 cc = (u32)kk * 2;
            u32 ah0[4], ah1[4];
            LDM4(ah0, buf + R_A + swz(r_a,      cc + ca));
            LDM4(ah1, buf + R_A + swz(r_a + 16, cc + ca));

            #pragma unroll
            for (int p = 0; p < 4; p++) {
                u32 bh[4], bl[4];
                u32 so = swz(r_b + (u32)p * 16, cc + cb);
                LDM4(bh, buf + R_BH + so);
                LDM4(bl, buf + R_BL + so);
                int n0 = p * 2;
                MMA(acc[0][n0],   ah0[0], ah0[1], ah0[2], ah0[3], bh[0], bh[1]);
                MMA(acc[0][n0+1], ah0[0], ah0[1], ah0[2], ah0[3], bh[2], bh[3]);
                MMA(acc[1][n0],   ah1[0], ah1[1], ah1[2], ah1[3], bh[0], bh[1]);
                MMA(acc[1][n0+1], ah1[0], ah1[1], ah1[2], ah1[3], bh[2], bh[3]);
                MMA(acc[0][n0],   ah0[0], ah0[1], ah0[2], ah0[3], bl[0], bl[1]);
                MMA(acc[0][n0+1], ah0[0], ah0[1], ah0[2], ah0[3], bl[2], bl[3]);
                MMA(acc[1][n0],   ah1[0], ah1[1], ah1[2], ah1[3], bl[0], bl[1]);
                MMA(acc[1][n0+1], ah1[0], ah1[1], ah1[2], ah1[3], bl[2], bl[3]);
            }
        }
        if (c + 2 < NC) ISSUE(c + 2, ist);
        st  = (st  == 2) ? 0 : st  + 1;
        ist = (ist == 2) ? 0 : ist + 1;
    }
    #undef ISSUE
}

// ---------------- kernel 5: FFN1 ----------------
__global__ void __launch_bounds__(256, 2) ffn1_kernel(const float* __restrict__ b1)
{
    int tile = blockIdx.y;
    if (tile >= g_ntiles) return;
    int e    = g_tile_exp[tile];
    int row0 = g_tile_row0[tile];
    int rows = g_tile_rows[tile];
    int n0b  = blockIdx.x * 128;

    extern __shared__ u16 smem_dyn[];
    u32 sb  = smem_u32(smem_dyn);
    int tid = threadIdx.x;
    int seg = (tid & 1) * 16;

    int arow = row0 + min(tid >> 1, rows - 1);
    const u16* aP = g_xh + (size_t)arow * D_MODEL + seg;
    size_t boff = ((size_t)e * HIDDEN + n0b + (tid >> 1)) * D_MODEL + seg;
    const u16* bH = g_w1hi + boff;
    const u16* bL = g_w1lo + boff;

    float acc[2][8][4];
    #pragma unroll
    for (int i = 0; i < 2; i++)
        #pragma unroll
        for (int j = 0; j < 8; j++)
            #pragma unroll
            for (int q = 0; q < 4; q++) acc[i][j][q] = 0.0f;

    run_gemm(sb, aP, bH, bL, D_MODEL / 32, tid, acc);

    int l  = tid & 31;
    int wm = (tid >> 5) & 3;
    int wn = (tid >> 5) >> 2;
    int g  = l >> 2;
    int t  = l & 3;
    const float* be = b1 + (size_t)e * HIDDEN + n0b + wn * 64;

    #pragma unroll
    for (int mf = 0; mf < 2; mf++)
        #pragma unroll
        for (int rr = 0; rr < 2; rr++) {
            int m = wm * 32 + mf * 16 + g + rr * 8;
            if (m < rows) {
                size_t ro = (size_t)(row0 + m) * HIDDEN + n0b + wn * 64;
                #pragma unroll
                for (int nb = 0; nb < 8; nb++) {
                    int nc = nb * 8 + t * 2;
                    float2 bb = *(const float2*)(be + nc);
                    float f0 = gelu_exact(acc[mf][nb][rr * 2 + 0] + bb.x);
                    float f1 = gelu_exact(acc[mf][nb][rr * 2 + 1] + bb.y);
                    u32 hp = (u32)__half_as_ushort(__float2half(f0))
                           | ((u32)__half_as_ushort(__float2half(f1)) << 16);
                    *(u32*)(g_hh + ro + nc) = hp;
                }
            }
        }
}

// ---------------- kernel 6: FFN2 ----------------
__global__ void __launch_bounds__(256, 2) ffn2_kernel(
    const float* __restrict__ b2, float* __restrict__ out)
{
    int tile = blockIdx.y;
    if (tile >= g_ntiles) return;
    int e    = g_tile_exp[tile];
    int row0 = g_tile_row0[tile];
    int rows = g_tile_rows[tile];
    int n0b  = blockIdx.x * 128;

    extern __shared__ u16 smem_dyn[];
    u32 sb  = smem_u32(smem_dyn);
    int tid = threadIdx.x;
    int seg = (tid & 1) * 16;

    int arow = row0 + min(tid >> 1, rows - 1);
    const u16* aP = g_hh + (size_t)arow * HIDDEN + seg;
    size_t boff = ((size_t)e * D_MODEL + n0b + (tid >> 1)) * HIDDEN + seg;
    const u16* bH = g_w2hi + boff;
    const u16* bL = g_w2lo + boff;

    float acc[2][8][4];
    #pragma unroll
    for (int i = 0; i < 2; i++)
        #pragma unroll
        for (int j = 0; j < 8; j++)
            #pragma unroll
            for (int q = 0; q < 4; q++) acc[i][j][q] = 0.0f;

    run_gemm(sb, aP, bH, bL, HIDDEN / 32, tid, acc);

    int l  = tid & 31;
    int wm = (tid >> 5) & 3;
    int wn = (tid >> 5) >> 2;
    int g  = l >> 2;
    int t  = l & 3;
    const float* be = b2 + (size_t)e * D_MODEL + n0b + wn * 64;

    #pragma unroll
    for (int mf = 0; mf < 2; mf++)
        #pragma unroll
        for (int rr = 0; rr < 2; rr++) {
            int m = wm * 32 + mf * 16 + g + rr * 8;
            if (m < rows) {
                int tok = g_perm[row0 + m];
                float w = g_wsel[tok];
                float* ob = out + (size_t)tok * D_MODEL + n0b + wn * 64;
                #pragma unroll
                for (int nb = 0; nb < 8; nb++) {
                    int nc = nb * 8 + t * 2;
                    float2 bb = *(const float2*)(be + nc);
                    float2 v;
                    v.x = w * (acc[mf][nb][rr * 2 + 0] + bb.x);
                    v.y = w * (acc[mf][nb][rr * 2 + 1] + bb.y);
                    *(float2*)(ob + nc) = v;
                }
            }
        }
}

// ---------------- kernel 7: aux loss (tiny, reads g_imp) ----------------
__global__ void aux_kernel(float* __restrict__ out, int T) {
    if (threadIdx.x == 0 && blockIdx.x == 0) {
        float s = 0.0f;
        #pragma unroll
        for (int e = 0; e < N_EXP; e++) {
            float im = (float)(g_imp[e] / (double)T);
            float d = im - 0.125f;
            s += d * d;
        }
        out[(size_t)T * D_MODEL] = s * (1.0f / 8.0f);
    }
}

// ---------------- launch ----------------
extern "C" void kernel_launch(void* const* d_in, const int* in_sizes, int n_in,
                              void* d_out, int out_size)
{
    const float* x  = (const float*)d_in[0];
    const float* u  = (const float*)d_in[1];
    const float* rw = (const float*)d_in[2];
    const float* rb = (const float*)d_in[3];
    const float* w1 = (const float*)d_in[4];
    const float* b1 = (const float*)d_in[5];
    const float* w2 = (const float*)d_in[6];
    const float* b2 = (const float*)d_in[7];
    float* out = (float*)d_out;

    int T = in_sizes[0] / D_MODEL;   // 8192

    cudaFuncSetAttribute(ffn1_kernel, cudaFuncAttributeMaxDynamicSharedMemorySize, SMEM_TOT);
    cudaFuncSetAttribute(ffn2_kernel, cudaFuncAttributeMaxDynamicSharedMemorySize, SMEM_TOT);

    init_kernel<<<1, 32>>>();
    router_kernel<<<T / 8, 256>>>(x, u, rw, rb, T);
    scatter_kernel<<<1, 1024>>>(T);
    convx_kernel<<<(T * 128 + 255) / 256, 256>>>(x, T);

    dim3 cb(32, 8);
    convT_kernel<D_MODEL, HIDDEN, 1><<<dim3(HIDDEN / 32, D_MODEL / 32, N_EXP), cb>>>(w1);
    convT_kernel<HIDDEN, D_MODEL, 2><<<dim3(D_MODEL / 32, HIDDEN / 32, N_EXP), cb>>>(w2);

    int max_tiles = T / TILE_M + N_EXP;
    ffn1_kernel<<<dim3(HIDDEN / 128, max_tiles), 256, SMEM_TOT>>>(b1);
    ffn2_kernel<<<dim3(D_MODEL / 128, max_tiles), 256, SMEM_TOT>>>(b2, out);

    aux_kernel<<<1, 32>>>(out, T);
}

// round 17
// speedup vs baseline: 2.8027x; 1.3809x over previous
#include <cuda_runtime.h>
#include <cuda_fp16.h>
#include <math.h>

#define D_MODEL 512
#define N_EXP   8
#define HIDDEN  2048
#define T_MAX   8192
#define TILE_M  128
#define MAX_TILES (T_MAX/TILE_M + N_EXP)

typedef unsigned int u32;
typedef unsigned short u16;

// swizzled smem: region = 128 logical rows x 32 fp16 (64B), packed as
// 64 phys rows x 128B with XOR swizzle; region = 8192 B, stage = 2 regions (A, B).
#define R_A  0
#define R_B  8192
#define BUF_B 16384
#define NSTAGE 3
#define SMEM_TOT (NSTAGE * BUF_B)   // 49152 B

// ---------------- scratch (device globals, no allocation) ----------------
__device__ __align__(16) u16 g_xh[(size_t)T_MAX * D_MODEL];           // fp16 x (rounded)
__device__ __align__(16) u16 g_w1h[(size_t)N_EXP * HIDDEN * D_MODEL]; // [E][H][D] transposed fp16
__device__ __align__(16) u16 g_w2h[(size_t)N_EXP * D_MODEL * HIDDEN]; // [E][D][H] transposed fp16
__device__ __align__(16) u16 g_hh[(size_t)T_MAX * HIDDEN];            // fp16 h (rounded)
__device__ int    g_perm[T_MAX];
__device__ int    g_tok_exp[T_MAX];
__device__ float  g_wsel[T_MAX];
__device__ double g_imp[N_EXP];
__device__ int    g_tile_exp[MAX_TILES];
__device__ int    g_tile_row0[MAX_TILES];
__device__ int    g_tile_rows[MAX_TILES];
__device__ int    g_ntiles;

__device__ __forceinline__ float gelu_exact(float v) {
    return 0.5f * v * (1.0f + erff(v * 0.70710678118654752440f));
}
__device__ __forceinline__ u32 smem_u32(const void* p) {
    u32 a;
    asm("{ .reg .u64 t; cvta.to.shared.u64 t, %1; cvt.u32.u64 %0, t; }" : "=r"(a) : "l"(p));
    return a;
}
// swizzle: logical (row r in 0..127, 16B unit c in 0..3) -> byte offset in region
__device__ __forceinline__ u32 swz(u32 r, u32 c) {
    return ((r >> 1) << 7) | (((((r & 1) << 2) | c) ^ ((r >> 1) & 7)) << 4);
}

// ---- portable PTX (sm_80+): cp.async, ldmatrix, mma ----
#define CP16(d, s)  asm volatile("cp.async.cg.shared.global [%0], [%1], 16;" :: "r"(d), "l"(s))
#define CPCOMMIT()  asm volatile("cp.async.commit_group;" ::: "memory")
#define CPWAIT1()   asm volatile("cp.async.wait_group 1;" ::: "memory")
#define CPWAIT0()   asm volatile("cp.async.wait_group 0;" ::: "memory")

#define LDM4(r, a) \
    asm volatile("ldmatrix.sync.aligned.m8n8.x4.shared.b16 {%0,%1,%2,%3}, [%4];" \
        : "=r"((r)[0]), "=r"((r)[1]), "=r"((r)[2]), "=r"((r)[3]) : "r"(a))

#define MMA(ac, a0, a1, a2, a3, b0, b1) \
    asm volatile("mma.sync.aligned.m16n8k16.row.col.f32.f16.f16.f32 " \
        "{%0,%1,%2,%3},{%4,%5,%6,%7},{%8,%9},{%0,%1,%2,%3};" \
        : "+f"((ac)[0]), "+f"((ac)[1]), "+f"((ac)[2]), "+f"((ac)[3]) \
        : "r"(a0), "r"(a1), "r"(a2), "r"(a3), "r"(b0), "r"(b1))

// ---------------- kernel 0 ----------------
__global__ void init_kernel() {
    if (threadIdx.x < N_EXP) g_imp[threadIdx.x] = 0.0;
}

// ---------------- kernel 1: router (proven) ----------------
__global__ void __launch_bounds__(256) router_kernel(
    const float* __restrict__ x, const float* __restrict__ u,
    const float* __restrict__ rw, const float* __restrict__ rb, int T)
{
    __shared__ float s_imp[N_EXP];
    if (threadIdx.x < N_EXP) s_imp[threadIdx.x] = 0.0f;
    __syncthreads();

    int t    = blockIdx.x * 8 + (threadIdx.x >> 5);
    int lane = threadIdx.x & 31;

    if (t < T) {
        float acc[8];
        #pragma unroll
        for (int e = 0; e < 8; e++) acc[e] = 0.0f;
        const float* xr = x + (size_t)t * D_MODEL;
        for (int k = lane; k < D_MODEL; k += 32) {
            float xv = xr[k];
            float4 wa = *(const float4*)(rw + k * 8);
            float4 wb = *(const float4*)(rw + k * 8 + 4);
            acc[0] += xv * wa.x; acc[1] += xv * wa.y;
            acc[2] += xv * wa.z; acc[3] += xv * wa.w;
            acc[4] += xv * wb.x; acc[5] += xv * wb.y;
            acc[6] += xv * wb.z; acc[7] += xv * wb.w;
        }
        #pragma unroll
        for (int e = 0; e < 8; e++) {
            #pragma unroll
            for (int off = 16; off > 0; off >>= 1)
                acc[e] += __shfl_down_sync(0xffffffffu, acc[e], off);
        }
        if (lane == 0) {
            float logits[8];
            #pragma unroll
            for (int e = 0; e < 8; e++) logits[e] = acc[e] + rb[e];
            float m = logits[0];
            #pragma unroll
            for (int e = 1; e < 8; e++) m = fmaxf(m, logits[e]);
            float p[8]; float se = 0.0f;
            #pragma unroll
            for (int e = 0; e < 8; e++) { p[e] = expf(logits[e] - m); se += p[e]; }
            float inv = 1.0f / se;
            #pragma unroll
            for (int e = 0; e < 8; e++) atomicAdd(&s_imp[e], p[e] * inv);

            const float* ur = u + (size_t)t * 8;
            float z[8]; int best = 0; float zb = -1e30f;
            #pragma unroll
            for (int e = 0; e < 8; e++) {
                float g = -logf(-logf(ur[e]) + 1e-10f);
                z[e] = logits[e] + g;
                if (z[e] > zb) { zb = z[e]; best = e; }
            }
            float s2 = 0.0f;
            #pragma unroll
            for (int e = 0; e < 8; e++) s2 += expf(z[e] - zb);
            float y = 1.0f / s2;
            g_tok_exp[t] = best;
            g_wsel[t]    = (1.0f - y) + y;
        }
    }
    __syncthreads();
    if (threadIdx.x < N_EXP)
        atomicAdd(&g_imp[threadIdx.x], (double)s_imp[threadIdx.x]);
}

// ---------------- kernel 2: scatter + tiles (proven) ----------------
__global__ void scatter_kernel(int T) {
    __shared__ int s_cnt[N_EXP];
    __shared__ int s_run[N_EXP];
    int tid = threadIdx.x;
    if (tid < N_EXP) s_cnt[tid] = 0;
    __syncthreads();
    for (int t = tid; t < T; t += blockDim.x)
        atomicAdd(&s_cnt[g_tok_exp[t]], 1);
    __syncthreads();
    if (tid == 0) {
        int off = 0, nt = 0;
        for (int e = 0; e < N_EXP; e++) {
            int c = s_cnt[e];
            s_run[e] = off;
            for (int m = 0; m < c; m += TILE_M) {
                g_tile_exp[nt]  = e;
                g_tile_row0[nt] = off + m;
                g_tile_rows[nt] = min(TILE_M, c - m);
                nt++;
            }
            off += c;
        }
        g_ntiles = nt;
    }
    __syncthreads();
    for (int t = tid; t < T; t += blockDim.x) {
        int pos = atomicAdd(&s_run[g_tok_exp[t]], 1);
        g_perm[pos] = t;
    }
}

// ---------------- kernel 3: gather + fp16 round x (perm order) ----------------
__global__ void __launch_bounds__(256) convx_kernel(const float* __restrict__ x, int T) {
    int idx = blockIdx.x * 256 + threadIdx.x;
    if (idx >= T * (D_MODEL / 4)) return;
    int row  = idx >> 7;
    int col4 = idx & 127;
    int tok  = g_perm[row];
    float4 v = ((const float4*)x)[(size_t)tok * 128 + col4];
    ushort4 H;
    H.x = __half_as_ushort(__float2half(v.x));
    H.y = __half_as_ushort(__float2half(v.y));
    H.z = __half_as_ushort(__float2half(v.z));
    H.w = __half_as_ushort(__float2half(v.w));
    *(ushort4*)(g_xh + (size_t)row * D_MODEL + col4 * 4) = H;
}

// ---------------- kernel 4: transpose + fp16 round weights ----------------
template<int R, int C, int WHICH>
__global__ void __launch_bounds__(256) convT_kernel(const float* __restrict__ src)
{
    __shared__ float tile[32][33];
    int e  = blockIdx.z;
    int c0 = blockIdx.x * 32, r0 = blockIdx.y * 32;
    int tx = threadIdx.x, ty = threadIdx.y;
    #pragma unroll
    for (int i = 0; i < 4; i++) {
        int r = r0 + ty + i * 8;
        tile[ty + i * 8][tx] = src[((size_t)e * R + r) * C + c0 + tx];
    }
    __syncthreads();
    u16* dh = (WHICH == 1) ? g_w1h : g_w2h;
    #pragma unroll
    for (int i = 0; i < 4; i++) {
        int c = c0 + ty + i * 8;
        int r = r0 + tx;
        float v = tile[tx][ty + i * 8];
        dh[((size_t)e * C + c) * R + r] = __half_as_ushort(__float2half(v));
    }
}

// ---------------- GEMM mainloop: 3-stage cp.async, swizzled, pure fp16 ---------
// CTA tile 128x128, 8 warps (4m x 2n), warp tile 32x64, K-chunk 32.
__device__ __forceinline__ void run_gemm(
    u32 sb, const u16* aP, const u16* bP,
    int NC, int tid, float acc[2][8][4])
{
    int l  = tid & 31;
    int wm = (tid >> 5) & 3;
    int wn = (tid >> 5) >> 2;

    u32 r_st = (u32)(tid >> 1);
    u32 u0   = (u32)(tid & 1) * 2;
    u32 d0 = swz(r_st, u0);
    u32 d1 = swz(r_st, u0 + 1);

    u32 r_a = (u32)(wm * 32 + (l & 7) + ((l & 8) ? 8 : 0));
    u32 ca  = (l & 16) ? 1u : 0u;
    u32 r_b = (u32)(wn * 64 + (l & 7) + ((l & 16) ? 8 : 0));
    u32 cb  = (l & 8) ? 1u : 0u;

    #define ISSUE(c, st) do { \
        u32 base = sb + (u32)(st) * BUF_B; \
        const u16* s_; \
        s_ = aP + (size_t)(c) * 32; CP16(base + R_A + d0, s_); CP16(base + R_A + d1, s_ + 8); \
        s_ = bP + (size_t)(c) * 32; CP16(base + R_B + d0, s_); CP16(base + R_B + d1, s_ + 8); \
        CPCOMMIT(); \
    } while (0)

    ISSUE(0, 0);
    if (NC > 1) ISSUE(1, 1);

    int st  = 0;
    int ist = 2;
    for (int c = 0; c < NC; c++) {
        if (c + 1 < NC) { CPWAIT1(); } else { CPWAIT0(); }
        __syncthreads();
        u32 buf = sb + (u32)st * BUF_B;

        #pragma unroll
        for (int kk = 0; kk < 2; kk++) {
            u32 cc = (u32)kk * 2;
            u32 ah0[4], ah1[4];
            LDM4(ah0, buf + R_A + swz(r_a,      cc + ca));
            LDM4(ah1, buf + R_A + swz(r_a + 16, cc + ca));

            #pragma unroll
            for (int p = 0; p < 4; p++) {
                u32 bh[4];
                LDM4(bh, buf + R_B + swz(r_b + (u32)p * 16, cc + cb));
                int n0 = p * 2;
                MMA(acc[0][n0],   ah0[0], ah0[1], ah0[2], ah0[3], bh[0], bh[1]);
                MMA(acc[0][n0+1], ah0[0], ah0[1], ah0[2], ah0[3], bh[2], bh[3]);
                MMA(acc[1][n0],   ah1[0], ah1[1], ah1[2], ah1[3], bh[0], bh[1]);
                MMA(acc[1][n0+1], ah1[0], ah1[1], ah1[2], ah1[3], bh[2], bh[3]);
            }
        }
        if (c + 2 < NC) ISSUE(c + 2, ist);
        st  = (st  == 2) ? 0 : st  + 1;
        ist = (ist == 2) ? 0 : ist + 1;
    }
    #undef ISSUE
}

// ---------------- kernel 5: FFN1 ----------------
__global__ void __launch_bounds__(256, 2) ffn1_kernel(const float* __restrict__ b1)
{
    int tile = blockIdx.y;
    if (tile >= g_ntiles) return;
    int e    = g_tile_exp[tile];
    int row0 = g_tile_row0[tile];
    int rows = g_tile_rows[tile];
    int n0b  = blockIdx.x * 128;

    extern __shared__ u16 smem_dyn[];
    u32 sb  = smem_u32(smem_dyn);
    int tid = threadIdx.x;
    int seg = (tid & 1) * 16;

    int arow = row0 + min(tid >> 1, rows - 1);
    const u16* aP = g_xh + (size_t)arow * D_MODEL + seg;
    size_t boff = ((size_t)e * HIDDEN + n0b + (tid >> 1)) * D_MODEL + seg;
    const u16* bP = g_w1h + boff;

    float acc[2][8][4];
    #pragma unroll
    for (int i = 0; i < 2; i++)
        #pragma unroll
        for (int j = 0; j < 8; j++)
            #pragma unroll
            for (int q = 0; q < 4; q++) acc[i][j][q] = 0.0f;

    run_gemm(sb, aP, bP, D_MODEL / 32, tid, acc);

    int l  = tid & 31;
    int wm = (tid >> 5) & 3;
    int wn = (tid >> 5) >> 2;
    int g  = l >> 2;
    int t  = l & 3;
    const float* be = b1 + (size_t)e * HIDDEN + n0b + wn * 64;

    #pragma unroll
    for (int mf = 0; mf < 2; mf++)
        #pragma unroll
        for (int rr = 0; rr < 2; rr++) {
            int m = wm * 32 + mf * 16 + g + rr * 8;
            if (m < rows) {
                size_t ro = (size_t)(row0 + m) * HIDDEN + n0b + wn * 64;
                #pragma unroll
                for (int nb = 0; nb < 8; nb++) {
                    int nc = nb * 8 + t * 2;
                    float2 bb = *(const float2*)(be + nc);
                    float f0 = gelu_exact(acc[mf][nb][rr * 2 + 0] + bb.x);
                    float f1 = gelu_exact(acc[mf][nb][rr * 2 + 1] + bb.y);
                    u32 hp = (u32)__half_as_ushort(__float2half(f0))
                           | ((u32)__half_as_ushort(__float2half(f1)) << 16);
                    *(u32*)(g_hh + ro + nc) = hp;
                }
            }
        }
}

// ---------------- kernel 6: FFN2 ----------------
__global__ void __launch_bounds__(256, 2) ffn2_kernel(
    const float* __restrict__ b2, float* __restrict__ out)
{
    int tile = blockIdx.y;
    if (tile >= g_ntiles) return;
    int e    = g_tile_exp[tile];
    int row0 = g_tile_row0[tile];
    int rows = g_tile_rows[tile];
    int n0b  = blockIdx.x * 128;

    extern __shared__ u16 smem_dyn[];
    u32 sb  = smem_u32(smem_dyn);
    int tid = threadIdx.x;
    int seg = (tid & 1) * 16;

    int arow = row0 + min(tid >> 1, rows - 1);
    const u16* aP = g_hh + (size_t)arow * HIDDEN + seg;
    size_t boff = ((size_t)e * D_MODEL + n0b + (tid >> 1)) * HIDDEN + seg;
    const u16* bP = g_w2h + boff;

    float acc[2][8][4];
    #pragma unroll
    for (int i = 0; i < 2; i++)
        #pragma unroll
        for (int j = 0; j < 8; j++)
            #pragma unroll
            for (int q = 0; q < 4; q++) acc[i][j][q] = 0.0f;

    run_gemm(sb, aP, bP, HIDDEN / 32, tid, acc);

    int l  = tid & 31;
    int wm = (tid >> 5) & 3;
    int wn = (tid >> 5) >> 2;
    int g  = l >> 2;
    int t  = l & 3;
    const float* be = b2 + (size_t)e * D_MODEL + n0b + wn * 64;

    #pragma unroll
    for (int mf = 0; mf < 2; mf++)
        #pragma unroll
        for (int rr = 0; rr < 2; rr++) {
            int m = wm * 32 + mf * 16 + g + rr * 8;
            if (m < rows) {
                int tok = g_perm[row0 + m];
                float w = g_wsel[tok];
                float* ob = out + (size_t)tok * D_MODEL + n0b + wn * 64;
                #pragma unroll
                for (int nb = 0; nb < 8; nb++) {
                    int nc = nb * 8 + t * 2;
                    float2 bb = *(const float2*)(be + nc);
                    float2 v;
                    v.x = w * (acc[mf][nb][rr * 2 + 0] + bb.x);
                    v.y = w * (acc[mf][nb][rr * 2 + 1] + bb.y);
                    *(float2*)(ob + nc) = v;
                }
            }
        }
}

// ---------------- kernel 7: aux loss (tiny, reads g_imp) ----------------
__global__ void aux_kernel(float* __restrict__ out, int T) {
    if (threadIdx.x == 0 && blockIdx.x == 0) {
        float s = 0.0f;
        #pragma unroll
        for (int e = 0; e < N_EXP; e++) {
            float im = (float)(g_imp[e] / (double)T);
            float d = im - 0.125f;
            s += d * d;
        }
        out[(size_t)T * D_MODEL] = s * (1.0f / 8.0f);
    }
}

// ---------------- launch ----------------
extern "C" void kernel_launch(void* const* d_in, const int* in_sizes, int n_in,
                              void* d_out, int out_size)
{
    const float* x  = (const float*)d_in[0];
    const float* u  = (const float*)d_in[1];
    const float* rw = (const float*)d_in[2];
    const float* rb = (const float*)d_in[3];
    const float* w1 = (const float*)d_in[4];
    const float* b1 = (const float*)d_in[5];
    const float* w2 = (const float*)d_in[6];
    const float* b2 = (const float*)d_in[7];
    float* out = (float*)d_out;

    int T = in_sizes[0] / D_MODEL;   // 8192

    cudaFuncSetAttribute(ffn1_kernel, cudaFuncAttributeMaxDynamicSharedMemorySize, SMEM_TOT);
    cudaFuncSetAttribute(ffn2_kernel, cudaFuncAttributeMaxDynamicSharedMemorySize, SMEM_TOT);

    init_kernel<<<1, 32>>>();
    router_kernel<<<T / 8, 256>>>(x, u, rw, rb, T);
    scatter_kernel<<<1, 1024>>>(T);
    convx_kernel<<<(T * 128 + 255) / 256, 256>>>(x, T);

    dim3 cb(32, 8);
    convT_kernel<D_MODEL, HIDDEN, 1><<<dim3(HIDDEN / 32, D_MODEL / 32, N_EXP), cb>>>(w1);
    convT_kernel<HIDDEN, D_MODEL, 2><<<dim3(D_MODEL / 32, HIDDEN / 32, N_EXP), cb>>>(w2);

    int max_tiles = T / TILE_M + N_EXP;
    ffn1_kernel<<<dim3(HIDDEN / 128, max_tiles), 256, SMEM_TOT>>>(b1);
    ffn2_kernel<<<dim3(D_MODEL / 128, max_tiles), 256, SMEM_TOT>>>(b2, out);

    aux_kernel<<<1, 32>>>(out, T);
}